// round 14
// baseline (speedup 1.0000x reference)
#include <cuda_runtime.h>
#include <cuda_bf16.h>
#include <cstddef>
#include <cstdint>

// Soft-Viterbi DP (N=M=2048, 3 states m,x,y) in LINEAR space with per-thread
// power-of-2 scaling: E = exp(V - K*ln2); lse3 -> FFMA dot products.
// Boundary V=-1e8 -> exactly 0. Output: K*ln2 + log(em+ex+ey).
// (Math validated R9-R13: rel_err 3.3e-6.)
//
// R14: barrier-free single-CTA systolic array.
//  - 8 warps x 32 lanes x 8 columns. Lane l of warp w owns columns
//    [w*256 + l*8 + 1 .. +8], computes row i = s - l + 1 at its warp-local
//    step s (lane skew 1 row). Intra-warp edges via __shfl_up_sync.
//  - Inter-warp edges via SMEM rings (depth 64) + release/acquire head /
//    consumed counters. No __syncthreads in the loop; warps free-run with
//    ring back-pressure (slack 56 rows).
//  - exp(theta) precomputed chip-wide into 6 float4 planes laid out by
//    (row, tid) -> every DP theta load is a coalesced LDG.128.

#define NN 2048
#define MM 2048
#define NT 256
#define NW 8
#define C  8
#define RD 64
#define RDM 63

static_assert(NT * C == MM, "column coverage");

// 6 planes x NN*NT float4 = 50.3 MB scratch (L2-resident on replays).
__device__ float4 g_eth[6][(size_t)NN * NT];

__device__ __forceinline__ float exp2i(int n) {  // 2^n, clamped to normals
    n = max(-126, min(127, n));
    return __int_as_float((n + 127) << 23);
}
__device__ __forceinline__ int lds_acquire(uint32_t a) {
    int v;
    asm volatile("ld.acquire.cta.shared.b32 %0, [%1];" : "=r"(v) : "r"(a) : "memory");
    return v;
}
__device__ __forceinline__ void sts_release(uint32_t a, int v) {
    asm volatile("st.release.cta.shared.b32 [%0], %1;" :: "r"(a), "r"(v) : "memory");
}

// exp(theta) + relayout: g_eth[q][i*NT + t] = exp(theta[i, 8t..8t+7]) part q.
__global__ void eth_kernel(const float* __restrict__ theta) {
    const float4* t4 = reinterpret_cast<const float4*>(theta);
    const size_t gid = (size_t)blockIdx.x * blockDim.x + threadIdx.x;  // NN*NT
    const size_t src = (gid >> 8) * 1536 + (gid & 255) * 6;
#pragma unroll
    for (int q = 0; q < 6; ++q) {
        float4 v = t4[src + q];
        g_eth[q][gid] = make_float4(__expf(v.x), __expf(v.y),
                                    __expf(v.z), __expf(v.w));
    }
}

__global__ __launch_bounds__(NT, 1)
void ViterbiDecoder_5506148073875_kernel(const float* __restrict__ A,
                                         float* __restrict__ out) {
    __shared__ float4 ring[NW - 1][RD];
    __shared__ int    rhead[NW - 1];   // highest row published per boundary
    __shared__ int    rcons[NW - 1];   // highest row consumed (multiples of 32)

    const int tid = threadIdx.x;
    const int w = tid >> 5, l = tid & 31;

    if (tid < NW - 1) { rhead[tid] = 0; rcons[tid] = 0; }
    __syncthreads();  // the ONLY block barrier

    // SMEM 32-bit addresses for acquire/release ops.
    const uint32_t head_rd = (uint32_t)__cvta_generic_to_shared(&rhead[w > 0 ? w - 1 : 0]);
    const uint32_t cons_wr = (uint32_t)__cvta_generic_to_shared(&rcons[w > 0 ? w - 1 : 0]);
    const uint32_t head_wr = (uint32_t)__cvta_generic_to_shared(&rhead[w < NW - 1 ? w : 0]);
    const uint32_t cons_rd = (uint32_t)__cvta_generic_to_shared(&rcons[w < NW - 1 ? w : 0]);

    const float ea00 = expf(A[0]), ea01 = expf(A[1]), ea02 = expf(A[2]);
    const float ea10 = expf(A[3]), ea11 = expf(A[4]), ea12 = expf(A[5]);
    const float ea20 = expf(A[6]), ea21 = expf(A[7]), ea22 = expf(A[8]);

    float p[3 * C];
#pragma unroll
    for (int k = 0; k < 3 * C; ++k) p[k] = 0.f;  // row 0: V=-inf -> 0
    int K = 0;

    // Neighbor column (w*256 + l*8, 1-based) history:
    // h1 = row i (left), h2 = row i-1 (diag).
    float h1m = 0.f, h1x = 0.f, h1y = 0.f; int h1k = 0;
    float h2m = 0.f, h2x = 0.f, h2y = 0.f; int h2k = 0;

    int cached_head = 0, cached_cons = 0;

    float4 tb0[6], tb1[6], tb2[6];  // 3-deep theta row pipeline (zero-copy)

    auto step = [&](int s, float4 (&cur)[6], float4 (&fut)[6]) {
        const int i = s - l + 1;  // 1-based row this lane computes

        // Load row i+2 into fut (consumed 2 steps later as cur).
        const int rf = i + 2;
        if (rf >= 1 && rf <= NN) {
            const size_t b = (size_t)(rf - 1) * NT + tid;
#pragma unroll
            for (int q = 0; q < 6; ++q) fut[q] = g_eth[q][b];
        }

        if (i >= 1 && i <= NN) {
            float dm = h2m, dx = h2x, dy = h2y; int dk = h2k;
            float lm = h1m, lx = h1x, ly = h1y; const int lk = h1k;
            if (w == 0 && l == 0 && i == 1) { dm = 1.f; dk = 0; }  // V[0,0]

            // Align diag/left (cell 0 only) to own scale K.
            const float fd = exp2i(dk - K);
            const float fl = exp2i(lk - K);
            dm *= fd; dx *= fd; dy *= fd;
            lm *= fl; lx *= fl; ly *= fl;

            const float th[24] = {cur[0].x, cur[0].y, cur[0].z, cur[0].w,
                                  cur[1].x, cur[1].y, cur[1].z, cur[1].w,
                                  cur[2].x, cur[2].y, cur[2].z, cur[2].w,
                                  cur[3].x, cur[3].y, cur[3].z, cur[3].w,
                                  cur[4].x, cur[4].y, cur[4].z, cur[4].w,
                                  cur[5].x, cur[5].y, cur[5].z, cur[5].w};
            float n[3 * C];
#pragma unroll
            for (int c = 0; c < C; ++c) {
                const float cdm = (c == 0) ? dm : p[3*c - 3];  // diag: own prev row
                const float cdx = (c == 0) ? dx : p[3*c - 2];
                const float cdy = (c == 0) ? dy : p[3*c - 1];
                const float clm = (c == 0) ? lm : n[3*c - 3];  // left: this row
                const float clx = (c == 0) ? lx : n[3*c - 2];
                const float cly = (c == 0) ? ly : n[3*c - 1];
                n[3*c + 0] = th[3*c + 0] *
                    fmaf(cdm, ea00, fmaf(cdx, ea01, cdy * ea02));
                n[3*c + 1] = th[3*c + 1] *
                    fmaf(p[3*c], ea10, fmaf(p[3*c + 1], ea11, p[3*c + 2] * ea12));
                n[3*c + 2] = th[3*c + 2] *
                    fmaf(clm, ea20, fmaf(clx, ea21, cly * ea22));
            }

            // Tree max (depth 5), renorm so max lands in [1,2); bump K.
            float g0 = fmaxf(fmaxf(n[0],  n[1]),  fmaxf(n[2],  n[3]));
            float g1 = fmaxf(fmaxf(n[4],  n[5]),  fmaxf(n[6],  n[7]));
            float g2 = fmaxf(fmaxf(n[8],  n[9]),  fmaxf(n[10], n[11]));
            float g3 = fmaxf(fmaxf(n[12], n[13]), fmaxf(n[14], n[15]));
            float g4 = fmaxf(fmaxf(n[16], n[17]), fmaxf(n[18], n[19]));
            float g5 = fmaxf(fmaxf(n[20], n[21]), fmaxf(n[22], n[23]));
            const float mx = fmaxf(fmaxf(fmaxf(g0, g1), fmaxf(g2, g3)),
                                   fmaxf(g4, g5));
            const int   sh = ((__float_as_int(mx) >> 23) & 0xff) - 127;
            const float fn = exp2i(-sh);
#pragma unroll
            for (int k = 0; k < 3 * C; ++k) p[k] = n[k] * fn;
            K += sh;

            // Producer: publish last cell (col (w+1)*256) to ring w.
            if (l == 31 && w < NW - 1) {
                if (i - cached_cons > RD - 8) {
                    do { cached_cons = lds_acquire(cons_rd); }
                    while (i - cached_cons > RD - 8);
                }
                ring[w][i & RDM] =
                    make_float4(p[21], p[22], p[23], __int_as_float(K));
                sts_release(head_wr, i);
            }
            if (w == NW - 1 && l == 31 && i == NN)
                out[0] = (float)K * 0.69314718055994531f +
                         logf(p[21] + p[22] + p[23]);
        }

        // Edge to lane l+1 (warp-synchronous); rotate neighbor history.
        const float rm = __shfl_up_sync(0xffffffffu, p[21], 1);
        const float rx = __shfl_up_sync(0xffffffffu, p[22], 1);
        const float ry = __shfl_up_sync(0xffffffffu, p[23], 1);
        const int   rk = __shfl_up_sync(0xffffffffu, K, 1);

        h2m = h1m; h2x = h1x; h2y = h1y; h2k = h1k;
        const int inext = i + 1;
        if (l == 0) {
            if (w > 0) {
                if (inext >= 1 && inext <= NN) {
                    if (cached_head < inext) {
                        do { cached_head = lds_acquire(head_rd); }
                        while (cached_head < inext);
                    }
                    const float4 e = ring[w - 1][inext & RDM];
                    h1m = e.x; h1x = e.y; h1y = e.z; h1k = __float_as_int(e.w);
                    if ((inext & 31) == 0) sts_release(cons_wr, inext);
                }
            } else {
                h1m = 0.f; h1x = 0.f; h1y = 0.f; h1k = 0;  // V[i,0] = -inf
            }
        } else {
            h1m = rm; h1x = rx; h1y = ry; h1k = rk;
        }
    };

    // s runs -3 .. 2078 (2082 = 3*694 iterations; guards handle ramp/drain).
    // cur at step s = tb[s mod 3]; fut at step s = tb[(s+2) mod 3].
    for (int s = -3; s < NN + 31; s += 3) {
        step(s,     tb0, tb2);
        step(s + 1, tb1, tb0);
        step(s + 2, tb2, tb1);
    }
}

extern "C" void kernel_launch(void* const* d_in, const int* in_sizes, int n_in,
                              void* d_out, int out_size) {
    const float* theta = (const float*)d_in[0];
    const float* A     = (const float*)d_in[1];
    if (n_in >= 2 && in_sizes[0] == 9) {  // defensive: swap if order differs
        theta = (const float*)d_in[1];
        A     = (const float*)d_in[0];
    }
    eth_kernel<<<(NN * NT) / 256, 256>>>(theta);
    ViterbiDecoder_5506148073875_kernel<<<1, NT>>>(A, (float*)d_out);
}

// round 16
// speedup vs baseline: 1.6085x; 1.6085x over previous
#include <cuda_runtime.h>
#include <cuda_bf16.h>
#include <cstddef>
#include <cstdint>

// Soft-Viterbi DP (N=M=2048, 3 states m,x,y) in LINEAR space with power-of-2
// scaling: E = exp(V - K*ln2); lse3 -> FFMA dot products. Boundary V=-1e8 ->
// exactly 0. Output: K*ln2 + log(em+ex+ey). (Math validated R9-R14, 3.3e-6.)
//
// R16: tiled block-wavefront across KERNEL LAUNCHES (deterministic multi-SM).
//  - 16x16 tiles of 128x128 cells. One launch per tile anti-diagonal (31);
//    tiles on a diagonal run concurrently on different SMs (1 warp each).
//  - Inter-tile edges via global float4 arrays gH (horizontal: V[a*128, j])
//    and gV (vertical: V[i, b*128]); launch ordering = synchronization.
//  - Intra-tile: 32-lane warp systolic, 4 cols/lane, lane skew 1 row,
//    __shfl_up edge stream. p initialized from the top edge => inactive-lane
//    shuffles automatically deliver the diagonal edge values.
//  - exp(theta) precomputed chip-wide into 3 float4 planes indexed by
//    (row, colgroup) -> coalesced, MUFU-free DP loop.
//  - R15->R16 fix: lane-0 left-edge queue refill loads row i+3 (was i+4,
//    which shifted the left edge by one row from local row 4 onward).

#define NNR 2048
#define GT  512            // column groups of 4
#define TR  128            // tile rows
#define TBN 16             // tiles per dimension
#define WAVES (2 * TBN - 1)

__device__ float4 g_eth[3][(size_t)NNR * GT];   // exp(theta) planes (48 MB)
__device__ float4 gH[TBN + 1][NNR + 1];         // gH[a][j] = V[a*128, j]
__device__ float4 gV[TBN + 1][NNR + 1];         // gV[b][i] = V[i, b*128]

__device__ __forceinline__ float exp2i(int n) {  // 2^n, clamped to normals
    n = max(-126, min(127, n));
    return __int_as_float((n + 127) << 23);
}

// exp(theta) relayout + boundary-edge init (fused: saves a launch).
// g_eth[q][(i-1)*GT + t] = exp(theta[i-1, 4t .. 4t+3]) part q.
__global__ void eth_kernel(const float* __restrict__ theta) {
    const size_t gid = (size_t)blockIdx.x * blockDim.x + threadIdx.x;
    if (gid <= NNR) {
        const float4 z   = make_float4(0.f, 0.f, 0.f, 0.f);
        const float4 one = make_float4(1.f, 0.f, 0.f, 0.f);  // V[0,0], K=0
        gH[0][gid] = gid ? z : one;   // V[0,j>0] = -inf -> 0
        gV[0][gid] = gid ? z : one;   // V[i>0,0] = -inf -> 0
        if (gid >= 1 && gid <= TBN) gV[gid][0] = z;  // corners V[0,b*128], b>0
    }
    const float4* t4 = reinterpret_cast<const float4*>(theta);
    const size_t src = (gid >> 9) * 1536 + (gid & 511) * 3;
#pragma unroll
    for (int q = 0; q < 3; ++q) {
        float4 v = t4[src + q];
        g_eth[q][gid] = make_float4(__expf(v.x), __expf(v.y),
                                    __expf(v.z), __expf(v.w));
    }
}

__global__ __launch_bounds__(32, 1)
void wave_kernel(const float* __restrict__ A, float* __restrict__ out,
                 int d, int a0) {
    const int a = a0 + (int)blockIdx.x;   // tile row
    const int b = d - a;                  // tile col
    const int l = threadIdx.x;
    const int rbase = a * TR;             // global rows rbase+1 .. rbase+TR
    const int cg = b * 32 + l;            // global column group
    const int jb = cg * 4 + 1;            // 1-based first column of this lane

    const float ea00 = __expf(A[0]), ea01 = __expf(A[1]), ea02 = __expf(A[2]);
    const float ea10 = __expf(A[3]), ea11 = __expf(A[4]), ea12 = __expf(A[5]);
    const float ea20 = __expf(A[6]), ea21 = __expf(A[7]), ea22 = __expf(A[8]);

    // ---- p init from the top edge gH[a][jb..jb+3] (align 4 cells to max K).
    float4 e0 = gH[a][jb],     e1 = gH[a][jb + 1];
    float4 e2 = gH[a][jb + 2], e3 = gH[a][jb + 3];
    const int k0 = __float_as_int(e0.w), k1 = __float_as_int(e1.w);
    const int k2 = __float_as_int(e2.w), k3 = __float_as_int(e3.w);
    int K = max(max(k0, k1), max(k2, k3));
    float p[12];
    {
        const float f0 = exp2i(k0 - K), f1 = exp2i(k1 - K);
        const float f2 = exp2i(k2 - K), f3 = exp2i(k3 - K);
        p[0] = e0.x * f0; p[1]  = e0.y * f0; p[2]  = e0.z * f0;
        p[3] = e1.x * f1; p[4]  = e1.y * f1; p[5]  = e1.z * f1;
        p[6] = e2.x * f2; p[7]  = e2.y * f2; p[8]  = e2.z * f2;
        p[9] = e3.x * f3; p[10] = e3.y * f3; p[11] = e3.z * f3;
    }

    // Neighbor history (lanes >= 1). Seed h1 with the top-edge diag value:
    // lane 1 consumes it as h2 at its first step; lanes >= 2 get their diag
    // from lane l-1's inactive shuffles of its top-edge-initialized p.
    float4 hs = gH[a][jb - 1];
    float h1m = hs.x, h1x = hs.y, h1y = hs.z; int h1k = __float_as_int(hs.w);
    float h2m = 0.f, h2x = 0.f, h2y = 0.f;    int h2k = 0;

    // Lane 0: left-tile edge register queue. Invariant at the START of the
    // step computing local row i: vD = left(row i-1), vL = left(row i),
    // q0 = left(row i+1), q1 = left(row i+2).
    float4 vD, vL, q0, q1;
    if (l == 0) {
        vD = gV[b][rbase + 0];  // corner V[rbase, b*128]
        vL = gV[b][rbase + 1];
        q0 = gV[b][rbase + 2];
        q1 = gV[b][rbase + 3];
    }

    // Theta pipeline: cur = exp(theta) row rbase+i, fut = row rbase+i+1.
    float4 c0, c1, c2, f0, f1, f2;
    {
        const size_t base = (size_t)rbase * GT + cg;  // row rbase+1
        c0 = g_eth[0][base]; c1 = g_eth[1][base]; c2 = g_eth[2][base];
    }

    for (int s = 0; s < TR + 31; ++s) {
        const int i = s - l + 1;  // local row (1..TR) this lane computes

        // Prefetch theta for local row i+1.
        const int rn = i + 1;
        if (rn >= 1 && rn <= TR) {
            const size_t bb = (size_t)(rbase + rn - 1) * GT + cg;
            f0 = g_eth[0][bb]; f1 = g_eth[1][bb]; f2 = g_eth[2][bb];
        }

        if (i >= 1 && i <= TR) {
            float lm, lx, ly, dm, dx, dy; int lk, dk;
            if (l == 0) {
                lm = vL.x; lx = vL.y; ly = vL.z; lk = __float_as_int(vL.w);
                dm = vD.x; dx = vD.y; dy = vD.z; dk = __float_as_int(vD.w);
            } else {
                lm = h1m; lx = h1x; ly = h1y; lk = h1k;
                dm = h2m; dx = h2x; dy = h2y; dk = h2k;
            }
            // Align cell-0 edge operands to own scale K.
            const float fl = exp2i(lk - K), fd = exp2i(dk - K);
            lm *= fl; lx *= fl; ly *= fl;
            dm *= fd; dx *= fd; dy *= fd;

            const float th[12] = {c0.x, c0.y, c0.z, c0.w,
                                  c1.x, c1.y, c1.z, c1.w,
                                  c2.x, c2.y, c2.z, c2.w};
            float n[12];
#pragma unroll
            for (int c = 0; c < 4; ++c) {
                const float cdm = (c == 0) ? dm : p[3*c - 3];  // diag
                const float cdx = (c == 0) ? dx : p[3*c - 2];
                const float cdy = (c == 0) ? dy : p[3*c - 1];
                const float clm = (c == 0) ? lm : n[3*c - 3];  // left (new row)
                const float clx = (c == 0) ? lx : n[3*c - 2];
                const float cly = (c == 0) ? ly : n[3*c - 1];
                n[3*c + 0] = th[3*c + 0] *
                    fmaf(cdm, ea00, fmaf(cdx, ea01, cdy * ea02));
                n[3*c + 1] = th[3*c + 1] *
                    fmaf(p[3*c], ea10, fmaf(p[3*c + 1], ea11, p[3*c + 2] * ea12));
                n[3*c + 2] = th[3*c + 2] *
                    fmaf(clm, ea20, fmaf(clx, ea21, cly * ea22));
            }

            // Renorm: max to [1,2), bump K.
            float g0 = fmaxf(fmaxf(n[0], n[1]),  fmaxf(n[2],  n[3]));
            float g1 = fmaxf(fmaxf(n[4], n[5]),  fmaxf(n[6],  n[7]));
            float g2 = fmaxf(fmaxf(n[8], n[9]),  fmaxf(n[10], n[11]));
            const float mx = fmaxf(g0, fmaxf(g1, g2));
            const int   sh = ((__float_as_int(mx) >> 23) & 0xff) - 127;
            const float fn = exp2i(-sh);
#pragma unroll
            for (int k = 0; k < 12; ++k) p[k] = n[k] * fn;
            K += sh;

            // Publish right edge (lane 31) and bottom edge (row TR).
            if (l == 31)
                gV[b + 1][rbase + i] =
                    make_float4(p[9], p[10], p[11], __int_as_float(K));
            if (i == TR) {
                const float kb = __int_as_float(K);
                gH[a + 1][jb]     = make_float4(p[0], p[1],  p[2],  kb);
                gH[a + 1][jb + 1] = make_float4(p[3], p[4],  p[5],  kb);
                gH[a + 1][jb + 2] = make_float4(p[6], p[7],  p[8],  kb);
                gH[a + 1][jb + 3] = make_float4(p[9], p[10], p[11], kb);
                if (a == TBN - 1 && b == TBN - 1 && l == 31)
                    out[0] = (float)K * 0.69314718055994531f +
                             logf(p[9] + p[10] + p[11]);
            }
        }

        // Edge stream to lane l+1 (warp-synchronous); rotate history.
        const float rm = __shfl_up_sync(0xffffffffu, p[9],  1);
        const float rx = __shfl_up_sync(0xffffffffu, p[10], 1);
        const float ry = __shfl_up_sync(0xffffffffu, p[11], 1);
        const int   rk = __shfl_up_sync(0xffffffffu, K, 1);
        h2m = h1m; h2x = h1x; h2y = h1y; h2k = h1k;
        h1m = rm;  h1x = rx;  h1y = ry;  h1k = rk;

        if (l == 0) {  // advance the left-edge queue: refill q1 with row i+3
            vD = vL; vL = q0; q0 = q1;
            const int rq = i + 3;
            if (rq >= 1 && rq <= TR) q1 = gV[b][rbase + rq];
        }

        if (rn >= 1 && rn <= TR) { c0 = f0; c1 = f1; c2 = f2; }
    }
}

extern "C" void kernel_launch(void* const* d_in, const int* in_sizes, int n_in,
                              void* d_out, int out_size) {
    const float* theta = (const float*)d_in[0];
    const float* A     = (const float*)d_in[1];
    if (n_in >= 2 && in_sizes[0] == 9) {  // defensive: swap if order differs
        theta = (const float*)d_in[1];
        A     = (const float*)d_in[0];
    }
    eth_kernel<<<(NNR * GT) / 256, 256>>>(theta);  // exp(theta) + edge init
    for (int d = 0; d < WAVES; ++d) {
        const int a0 = max(0, d - (TBN - 1));
        const int a1 = min(d, TBN - 1);
        wave_kernel<<<a1 - a0 + 1, 32>>>(A, (float*)d_out, d, a0);
    }
}